// round 16
// baseline (speedup 1.0000x reference)
#include <cuda_runtime.h>
#include <cuda_fp16.h>

#define B_ 512
#define S_ 168
#define F_ 12
#define H_ 128
#define O_ 3
#define S2_ (S_ * S_)
#define ROWS 8

typedef unsigned int u32;

// ---------------- device scratch ----------------
__device__ uint4 g_W0f[16 * 9 * 32];    // L0 fragments [tile][ks][lane] (K=144: x|pad|h)
__device__ uint4 g_W1f[16 * 16 * 32];   // L1 fragments [tile][ks][lane]
__device__ uint4 g_Hf[24 * 16 * 32];    // head fragments (per-rank blocks [ff1|ff2|gate])
__device__ float g_bh[384];
__device__ float g_T[3 * S2_];
__device__ float g_WfT[3 * S2_];
__device__ float g_mean[B_ * F_];
__device__ float g_x1[B_ * S_ * F_];
__device__ float g_x2[B_ * S_ * O_];
__device__ float g_x3[B_ * S_ * O_];
__device__ float g_hs[B_ * S_ * H_];

// ---------------- helpers ----------------
__device__ __forceinline__ float tanh_ap(float x) {
    float y;
    asm("tanh.approx.f32 %0, %1;" : "=f"(y) : "f"(x));
    return y;
}
__device__ __forceinline__ float siluf(float x) {
    return x * fmaf(0.5f, tanh_ap(0.5f * x), 0.5f);
}
__device__ __forceinline__ float sigf(float x) {
    return fmaf(0.5f, tanh_ap(0.5f * x), 0.5f);
}
__device__ __forceinline__ u32 hpack(float a, float b) {
    __half2 h = __floats2half2_rn(a, b);
    return *reinterpret_cast<u32*>(&h);
}
__device__ __forceinline__ void mma16816(float* d, uint4 A, u32 b0, u32 b1) {
    asm volatile(
        "mma.sync.aligned.m16n8k16.row.col.f32.f16.f16.f32 "
        "{%0,%1,%2,%3},{%4,%5,%6,%7},{%8,%9},{%0,%1,%2,%3};"
        : "+f"(d[0]), "+f"(d[1]), "+f"(d[2]), "+f"(d[3])
        : "r"(A.x), "r"(A.y), "r"(A.z), "r"(A.w), "r"(b0), "r"(b1));
}
#define CLUSTER_SYNC() do { \
    asm volatile("barrier.cluster.arrive.aligned;" ::: "memory"); \
    asm volatile("barrier.cluster.wait.aligned;" ::: "memory"); } while (0)

// remote 32-bit store whose completion adds 4 bytes to the REMOTE mbarrier's tx count
__device__ __forceinline__ void st_async32(u32 raddr, u32 v, u32 rmbar) {
    asm volatile(
        "st.async.shared::cluster.mbarrier::complete_tx::bytes.b32 [%0], %1, [%2];"
        :: "r"(raddr), "r"(v), "r"(rmbar) : "memory");
}
__device__ __forceinline__ void mbar_init(u32 a, u32 cnt) {
    asm volatile("mbarrier.init.shared.b64 [%0], %1;" :: "r"(a), "r"(cnt) : "memory");
}
__device__ __forceinline__ void mbar_expect(u32 a, u32 bytes) {
    asm volatile("mbarrier.arrive.expect_tx.shared.b64 _, [%0], %1;"
                 :: "r"(a), "r"(bytes) : "memory");
}
__device__ __forceinline__ void mbar_wait(u32 a, u32 parity) {
    asm volatile(
        "{\n\t.reg .pred P;\n"
        "W%=:\n\t"
        "mbarrier.try_wait.parity.acquire.cluster.shared::cta.b64 P, [%0], %1, 0x989680;\n\t"
        "@P bra D%=;\n\t"
        "bra W%=;\n"
        "D%=:\n\t}"
        :: "r"(a), "r"(parity) : "memory");
}

// weight element accessors
// L0 K layout: [0,12)=x, [12,16)=pad, [16,144)=h
__device__ __forceinline__ float w0_at(const float* W, int o, int k) {
    if (k < 12)  return W[o * 140 + k];
    if (k < 16)  return 0.f;
    return W[o * 140 + (k - 4)];
}
// head reorder: block r (192 rows) = [ff1(64r:64r+64); ff2(...); gate(...)]
__device__ __forceinline__ float wh_at(const float* f1, const float* f2,
                                       const float* ta, const float* tb, int m, int k) {
    int blk = m / 192, o = m % 192, base = blk * 64;
    if (o < 64)  return f1[(base + o) * 256 + k];
    if (o < 128) return f2[(base + o - 64) * 256 + k];
    return ta[(base + o - 128) * 256 + k] + tb[(base + o - 128) * 256 + k];
}

__device__ __forceinline__ float sff_contrib(const float* __restrict__ conv,
                                             const float* __restrict__ lin,
                                             int p, int seg, int pad, int so, int si) {
    int phase = so % p, q = so / p;
    float acc = 0.f;
    for (int kk = 0; kk < seg; ++kk) {
        int d = si - (kk * p + phase);
        float c = 0.f;
        if (d >= -pad && d <= pad) c = conv[d + pad];
        if (d == 0) c += 1.f;
        acc += lin[q * seg + kk] * c;
    }
    return acc;
}

// ---------------- merged prep: fragments + biases + T + WfT ----------------
__global__ void k_preall(const float* __restrict__ Wb0, const float* __restrict__ Wb1,
                         const float* __restrict__ Wff1, const float* __restrict__ Wff2,
                         const float* __restrict__ Wta, const float* __restrict__ Wtb,
                         const float* __restrict__ bff1, const float* __restrict__ bff2,
                         const float* __restrict__ bta, const float* __restrict__ btb,
                         const float* __restrict__ c3, const float* __restrict__ l3,
                         const float* __restrict__ c6, const float* __restrict__ l6,
                         const float* __restrict__ c12, const float* __restrict__ l12,
                         const float* __restrict__ c24, const float* __restrict__ l24,
                         const float* __restrict__ Wfits) {
    int idx = blockIdx.x * blockDim.x + threadIdx.x;
    const int N0 = 16 * 9 * 32, N1 = 16 * 16 * 32, NH = 24 * 16 * 32;
    const int NP = N0 + N1 + NH + 384;
    if (idx < N0 + N1 + NH) {
        int which, tile, ks, l, i = idx;
        if (i < N0)           { which = 0; tile = i / (9 * 32);  ks = (i / 32) % 9; }
        else if (i < N0 + N1) { which = 1; i -= N0; tile = i / (16 * 32); ks = (i / 32) % 16; }
        else                  { which = 2; i -= N0 + N1; tile = i / (16 * 32); ks = (i / 32) % 16; }
        l = i % 32;
        int g = l / 4, ti = l % 4;
        int r0 = tile * 16 + g, k0 = ks * 16 + ti * 2;
        float e[4][2];
        for (int half = 0; half < 2; half++) {
            for (int rr = 0; rr < 2; rr++) {
                for (int cc = 0; cc < 2; cc++) {
                    int o = r0 + rr * 8, k = k0 + half * 8 + cc;
                    float wv;
                    if (which == 0)      wv = w0_at(Wb0, o, k);
                    else if (which == 1) wv = Wb1[o * 256 + k];
                    else                 wv = wh_at(Wff1, Wff2, Wta, Wtb, o, k);
                    e[half * 2 + rr][cc] = wv;
                }
            }
        }
        uint4 out;
        out.x = hpack(e[0][0], e[0][1]);
        out.y = hpack(e[1][0], e[1][1]);
        out.z = hpack(e[2][0], e[2][1]);
        out.w = hpack(e[3][0], e[3][1]);
        if (which == 0)      g_W0f[idx] = out;
        else if (which == 1) g_W1f[idx - N0] = out;
        else                 g_Hf[idx - N0 - N1] = out;
    } else if (idx < NP) {
        int m = idx - N0 - N1 - NH;
        int blk = m / 192, o = m % 192, base = blk * 64;
        float b;
        if (o < 64)       b = bff1[base + o];
        else if (o < 128) b = bff2[base + o - 64];
        else              b = bta[base + o - 128] + btb[base + o - 128];
        g_bh[m] = b;
    } else if (idx < NP + 3 * S2_) {
        int j = idx - NP;
        int L = j / S2_, r = j % S2_;
        int so = r / S_, si = r % S_;
        float a = sff_contrib(c3 + L * 3, l3 + L * 56 * 56, 3, 56, 1, so, si)
                + sff_contrib(c6 + L * 7, l6 + L * 28 * 28, 6, 28, 3, so, si)
                + sff_contrib(c12 + L * 13, l12 + L * 14 * 14, 12, 14, 6, so, si)
                + sff_contrib(c24 + L * 25, l24 + L * 7 * 7, 24, 7, 12, so, si);
        g_T[L * S2_ + si * S_ + so] = 0.25f * a;
    } else if (idx < NP + 6 * S2_) {
        int j = idx - NP - 3 * S2_;
        int c = j / S2_, r = j % S2_;
        int s = r / S_, p = r % S_;
        g_WfT[c * S2_ + s * S_ + p] = Wfits[c * S2_ + p * S_ + s];
    }
}

__global__ void k_mean(const float* __restrict__ x) {
    int w = (blockIdx.x * blockDim.x + threadIdx.x) >> 5;
    int lane = threadIdx.x & 31;
    if (w >= B_ * F_) return;
    const float* p = x + w * S_;
    float s = 0.f;
    for (int i = lane; i < S_; i += 32) s += p[i];
#pragma unroll
    for (int o = 16; o; o >>= 1) s += __shfl_xor_sync(0xffffffffu, s, o);
    if (!lane) g_mean[w] = s * (1.f / (float)S_);
}

// ---------------- fused front ----------------
__global__ void k_front(const float* __restrict__ x) {
    __shared__ float xs[S_][F_];
    __shared__ float x1s[S_][4];
    int b = blockIdx.x, t = threadIdx.x;
    for (int i = t; i < S_ * F_; i += blockDim.x) {
        int si = i / F_, f = i % F_;
        xs[si][f] = x[b * F_ * S_ + f * S_ + si] - g_mean[b * F_ + f];
    }
    __syncthreads();
    if (t < S_) {
        float acc[F_];
#pragma unroll
        for (int f = 0; f < F_; f++) acc[f] = 0.f;
        for (int si = 0; si < S_; ++si) {
            float tw = g_T[si * S_ + t];
#pragma unroll
            for (int f = 0; f < F_; f++) acc[f] = fmaf(tw, xs[si][f], acc[f]);
        }
        float* o = g_x1 + (b * S_ + t) * F_;
#pragma unroll
        for (int f = 0; f < F_; f++) o[f] = acc[f];
        x1s[t][0] = acc[0]; x1s[t][1] = acc[1]; x1s[t][2] = acc[2];
    }
    __syncthreads();
    if (t < S_) {
        float a2[3] = {0.f, 0.f, 0.f}, a3[3] = {0.f, 0.f, 0.f};
        for (int si = 0; si < S_; ++si) {
            float t1 = g_T[S2_ + si * S_ + t];
            float t2 = g_T[2 * S2_ + si * S_ + t];
#pragma unroll
            for (int c = 0; c < 3; c++) {
                a2[c] = fmaf(t1, x1s[si][c], a2[c]);
                a3[c] = fmaf(t2, x1s[si][c], a3[c]);
            }
        }
#pragma unroll
        for (int c = 0; c < 3; c++) {
            g_x2[(b * S_ + t) * 3 + c] = a2[c];
            g_x3[(b * S_ + t) * 3 + c] = a3[c];
        }
    }
}

// ---------------- CfC recurrence: cluster-2, st.async, 512 threads ----------
// tx per step: mb_h = 256 x 4 B = 1024; mb_p = 512 x 8 B = 4096.
// Warp roles: L0 warps 0-7 (tile w); L1 all 16 warps (tile w, own-K half);
// head warps 0-11 (tile w, 4 chains); zb-fuse all threads; combine t<256.
// mbarrier waits are per-warp (divergence-safe) — no convergence rendezvous.
// SMEM (bytes):
//   [0,36864)       sW0 | [36864,102400) sW1 | [102400,200704) sHf
//   [200704,203392) in0 [8][168]h | [203392,207616) za [8][264]h
//   [207616,211712) pB col-major [256][8]h | [211712,215936) zb [8][264]h
//   [215936,222336) hdro [8][200]f | [222336,222352) mb_h, mb_p
__global__ void __launch_bounds__(512, 1) __cluster_dims__(2, 1, 1)
k_rnn(const float* __restrict__ bb0, const float* __restrict__ bb1) {
    extern __shared__ __align__(16) char s[];
    uint4*  sW0  = (uint4*)(s);
    uint4*  sW1  = (uint4*)(s + 36864);
    uint4*  sHf  = (uint4*)(s + 102400);
    __half* in0  = (__half*)(s + 200704);
    __half* za   = (__half*)(s + 203392);
    char*   pB   = (char*)(s + 207616);
    __half* zb   = (__half*)(s + 211712);
    float*  hdro = (float*)(s + 215936);

    const int t = threadIdx.x, w = t >> 5, l = t & 31, gg = l >> 2, ti = l & 3;
    u32 rank;
    asm("mov.u32 %0, %%cluster_ctarank;" : "=r"(rank));
    const u32 peer = rank ^ 1u;
    const int bb = (blockIdx.x >> 1) * ROWS;

    u32 base;
    asm("{ .reg .u64 a; cvta.to.shared.u64 a, %1; cvt.u32.u64 %0, a; }" : "=r"(base) : "l"(s));
    const u32 mb_h = base + 222336, mb_p = base + 222344;
    u32 in0_r, pB_r, mb_h_r, mb_p_r;
    asm("mapa.shared::cluster.u32 %0, %1, %2;" : "=r"(in0_r) : "r"(base + 200704), "r"(peer));
    asm("mapa.shared::cluster.u32 %0, %1, %2;" : "=r"(pB_r) : "r"(base + 207616), "r"(peer));
    asm("mapa.shared::cluster.u32 %0, %1, %2;" : "=r"(mb_h_r) : "r"(mb_h), "r"(peer));
    asm("mapa.shared::cluster.u32 %0, %1, %2;" : "=r"(mb_p_r) : "r"(mb_p), "r"(peer));

    // stage weights
    {
        const uint4* p0 = g_W0f + rank * 2304;
        for (int i = t; i < 2304; i += 512) sW0[i] = p0[i];
        for (int i = t; i < 4096; i += 512) {
            int tile = i >> 8, ksl = (i >> 5) & 7, lane = i & 31;
            sW1[i] = g_W1f[(tile * 16 + 8 * (int)rank + ksl) * 32 + lane];
        }
        const uint4* ph = g_Hf + rank * 6144;
        for (int i = t; i < 6144; i += 512) sHf[i] = ph[i];
    }
    for (int i = t; i < ROWS * 168; i += 512) in0[i] = __float2half(0.f);
    if (t == 0) {
        mbar_init(mb_h, 1);
        mbar_init(mb_p, 1);
        mbar_expect(mb_h, 0);      // h(-1)=0 present -> phase 0 completes now
        mbar_expect(mb_p, 4096);   // step-0 partials
    }
    __syncthreads();
    CLUSTER_SYNC();            // init + expects + zeroed h visible cluster-wide
    if (t < 96) {              // x(0)
        int r = t / 12, f = t - r * 12;
        in0[r * 168 + f] = __float2half(g_x1[(bb + r) * S_ * F_ + f]);
    }

    const int ra2 = 2 * ti, rb2 = 2 * ti + 1;
    const int hb = 192 * (int)rank;
    const int gob = (8 * (int)rank + (w & 7)) * 16;  // L0 out base (w<8)
    const int ko1 = 1 + 4 * (int)rank, kp1 = 1 + 4 * (int)peer;
    const int o0 = w * 16 + gg;                      // L1 tile col (all 16 warps)
    const bool l0w = (w < 8);
    const bool hdw = (w < 12);

    // bias preloads
    const float rb0a = l0w ? bb0[gob + gg] : 0.f;
    const float rb0b = l0w ? bb0[gob + gg + 8] : 0.f;
    const float rb1c0 = bb1[o0], rb1c1 = bb1[o0 + 8];
    const float hea = hdw ? g_bh[hb + w * 16 + gg] : 0.f;
    const float heb = hdw ? g_bh[hb + w * 16 + gg + 8] : 0.f;

    for (int step = 0; step < S_; ++step) {
        const u32 par = step & 1u;
        __syncthreads();   // local in0 (x(s), own h(s-1)) visible

        // ======== L0 (warps 0-7): own tile, x + own-h, [wait], peer-h ========
        float dA[4], dB[4];
        if (l0w) {
            dA[0] = dA[1] = rb0a;
            dA[2] = dA[3] = rb0b;
            dB[0] = dB[1] = dB[2] = dB[3] = 0.f;
            {
                u32 b0 = *(const u32*)&in0[gg * 168 + ti * 2];
                u32 b1 = *(const u32*)&in0[gg * 168 + ti * 2 + 8];
                mma16816(dA, sW0[(w * 9 + 0) * 32 + l], b0, b1);
            }
#pragma unroll
            for (int j = 0; j < 4; j++) {
                int ks = ko1 + j;
                u32 b0 = *(const u32*)&in0[gg * 168 + ks * 16 + ti * 2];
                u32 b1 = *(const u32*)&in0[gg * 168 + ks * 16 + ti * 2 + 8];
                mma16816((j & 1) ? dB : dA, sW0[(w * 9 + ks) * 32 + l], b0, b1);
            }
            mbar_wait(mb_h, par);   // per-warp wait; only L0 warps block here
            // post next h expect (t0 is in an L0 warp). Ordered before any peer
            // h(s)-complete: that needs our partials(s), stored after za sync.
            if (t == 0 && step + 1 < S_) mbar_expect(mb_h, 1024);
#pragma unroll
            for (int j = 0; j < 4; j++) {
                int ks = kp1 + j;
                u32 b0 = *(const u32*)&in0[gg * 168 + ks * 16 + ti * 2];
                u32 b1 = *(const u32*)&in0[gg * 168 + ks * 16 + ti * 2 + 8];
                mma16816((j & 1) ? dA : dB, sW0[(w * 9 + ks) * 32 + l], b0, b1);
            }
            int i0 = ra2 * 264 + gob + gg, i1 = rb2 * 264 + gob + gg;
            za[i0]     = __float2half(siluf(dA[0] + dB[0]));
            za[i1]     = __float2half(siluf(dA[1] + dB[1]));
            za[i0 + 8] = __float2half(siluf(dA[2] + dB[2]));
            za[i1 + 8] = __float2half(siluf(dA[3] + dB[3]));
        }
        __syncthreads();   // za complete; orders t0's h-expect before partial sends

        // ======== L1 K-split (all 16 warps): tile w over own za half ========
        float d0[4];
        {
            float d0a[4] = {0.f, 0.f, 0.f, 0.f}, d0b[4] = {0.f, 0.f, 0.f, 0.f};
#pragma unroll
            for (int j = 0; j < 8; j++) {
                int ksg = 8 * (int)rank + j;
                u32 b0 = *(const u32*)&za[gg * 264 + ksg * 16 + ti * 2];
                u32 b1 = *(const u32*)&za[gg * 264 + ksg * 16 + ti * 2 + 8];
                mma16816((j & 1) ? d0b : d0a, sW1[(w * 8 + j) * 32 + l], b0, b1);
            }
#pragma unroll
            for (int j = 0; j < 4; j++) d0[j] = d0a[j] + d0b[j];
            st_async32(pB_r + o0 * 16 + ti * 4,       hpack(d0[0], d0[1]), mb_p_r);
            st_async32(pB_r + (o0 + 8) * 16 + ti * 4, hpack(d0[2], d0[3]), mb_p_r);
        }
        float xreg = 0.f;
        if (t < 96 && step + 1 < S_) {
            int r = t / 12, f = t - r * 12;
            xreg = __ldg(&g_x1[((bb + r) * S_ + step + 1) * F_ + f]);
        }
        mbar_wait(mb_p, par);   // peer partial landed (all warps need pB)
        // post next p expect. Ordered before peer partial(s+1)-complete: that
        // needs our h(s), sent after the hdro __syncthreads below.
        if (t == 0 && step + 1 < S_) mbar_expect(mb_p, 4096);

        // ======== zb fuse: regs + pB + bias (each thread: tile w cols) ======
        {
            float2 q;
            q = __half22float2(*(const __half2*)(pB + o0 * 16 + ti * 4));
            zb[ra2 * 264 + o0] = __float2half(siluf(d0[0] + q.x + rb1c0));
            zb[rb2 * 264 + o0] = __float2half(siluf(d0[1] + q.y + rb1c0));
            q = __half22float2(*(const __half2*)(pB + (o0 + 8) * 16 + ti * 4));
            zb[ra2 * 264 + o0 + 8] = __float2half(siluf(d0[2] + q.x + rb1c1));
            zb[rb2 * 264 + o0 + 8] = __float2half(siluf(d0[3] + q.y + rb1c1));
        }
        __syncthreads();   // zb complete

        // ======== head (warps 0-11): tile w, K=256, 4 chains ========
        if (hdw) {
            float ea[4], eb[4], ec[4], ed[4];
            ea[0] = ea[1] = hea;
            ea[2] = ea[3] = heb;
#pragma unroll
            for (int j = 0; j < 4; j++) { eb[j] = 0.f; ec[j] = 0.f; ed[j] = 0.f; }
#pragma unroll
            for (int ks = 0; ks < 16; ks += 4) {
                u32 b0, b1;
                b0 = *(const u32*)&zb[gg * 264 + ks * 16 + ti * 2];
                b1 = *(const u32*)&zb[gg * 264 + ks * 16 + ti * 2 + 8];
                mma16816(ea, sHf[(w * 16 + ks) * 32 + l], b0, b1);
                b0 = *(const u32*)&zb[gg * 264 + (ks + 1) * 16 + ti * 2];
                b1 = *(const u32*)&zb[gg * 264 + (ks + 1) * 16 + ti * 2 + 8];
                mma16816(eb, sHf[(w * 16 + ks + 1) * 32 + l], b0, b1);
                b0 = *(const u32*)&zb[gg * 264 + (ks + 2) * 16 + ti * 2];
                b1 = *(const u32*)&zb[gg * 264 + (ks + 2) * 16 + ti * 2 + 8];
                mma16816(ec, sHf[(w * 16 + ks + 2) * 32 + l], b0, b1);
                b0 = *(const u32*)&zb[gg * 264 + (ks + 3) * 16 + ti * 2];
                b1 = *(const u32*)&zb[gg * 264 + (ks + 3) * 16 + ti * 2 + 8];
                mma16816(ed, sHf[(w * 16 + ks + 3) * 32 + l], b0, b1);
            }
            int ob = w * 16;
            hdro[ra2 * 200 + ob + gg]     = (ea[0] + eb[0]) + (ec[0] + ed[0]);
            hdro[rb2 * 200 + ob + gg]     = (ea[1] + eb[1]) + (ec[1] + ed[1]);
            hdro[ra2 * 200 + ob + gg + 8] = (ea[2] + eb[2]) + (ec[2] + ed[2]);
            hdro[rb2 * 200 + ob + gg + 8] = (ea[3] + eb[3]) + (ec[3] + ed[3]);
        }
        __syncthreads();   // hdro ready; orders t0's p-expect before h sends

        // ======== combine (t<256): thread -> (row, 2 adjacent j) ========
        if (t < 256) {
            int row = t >> 5, j0 = (t & 31) * 2;
            float2 v1 = *(const float2*)&hdro[row * 200 + j0];
            float2 v2 = *(const float2*)&hdro[row * 200 + 64 + j0];
            float2 vg = *(const float2*)&hdro[row * 200 + 128 + j0];
            float f1x = tanh_ap(v1.x), f2x = tanh_ap(v2.x), sgx = sigf(vg.x);
            float f1y = tanh_ap(v1.y), f2y = tanh_ap(v2.y), sgy = sigf(vg.y);
            float h0 = f1x + sgx * (f2x - f1x);
            float h1 = f1y + sgy * (f2y - f1y);
            int jg = 64 * (int)rank + j0;
            int idx = row * 168 + 16 + jg;
            u32 hh = hpack(h0, h1);
            if (step + 1 < S_) st_async32(in0_r + idx * 2, hh, mb_h_r);  // send first
            *(u32*)&in0[idx] = hh;
            *(float2*)&g_hs[((size_t)(bb + row) * S_ + step) * H_ + jg] =
                make_float2(h0, h1);
        }
        if (t < 96 && step + 1 < S_) {
            int r = t / 12, f = t - r * 12;
            in0[r * 168 + f] = __float2half(xreg);
        }
    }
    CLUSTER_SYNC();   // drain
}

// ---------------- fused back ----------------
__global__ void k_back(const float* __restrict__ Wfc, const float* __restrict__ bfc,
                       float* __restrict__ out) {
    __shared__ float r1s[S_][4];
    int b = blockIdx.x, t = threadIdx.x;
    int w = t >> 5, lane = t & 31;
    for (int s = w; s < S_; s += 8) {
        const float* h = g_hs + (size_t)(b * S_ + s) * H_;
        float a0 = 0.f, a1 = 0.f, a2 = 0.f;
        for (int i = lane; i < H_; i += 32) {
            float hv = h[i];
            a0 = fmaf(hv, Wfc[i], a0);
            a1 = fmaf(hv, Wfc[H_ + i], a1);
            a2 = fmaf(hv, Wfc[2 * H_ + i], a2);
        }
#pragma unroll
        for (int o = 16; o; o >>= 1) {
            a0 += __shfl_xor_sync(0xffffffffu, a0, o);
            a1 += __shfl_xor_sync(0xffffffffu, a1, o);
            a2 += __shfl_xor_sync(0xffffffffu, a2, o);
        }
        if (!lane) {
            r1s[s][0] = a0 + bfc[0] + g_x3[(b * S_ + s) * 3 + 0];
            r1s[s][1] = a1 + bfc[1] + g_x3[(b * S_ + s) * 3 + 1];
            r1s[s][2] = a2 + bfc[2] + g_x3[(b * S_ + s) * 3 + 2];
        }
    }
    __syncthreads();
    if (t < S_) {
        float a0 = g_mean[b * F_ + 0] + g_x2[(b * S_ + t) * 3 + 0];
        float a1 = g_mean[b * F_ + 1] + g_x2[(b * S_ + t) * 3 + 1];
        float a2 = g_mean[b * F_ + 2] + g_x2[(b * S_ + t) * 3 + 2];
        for (int s = 0; s < S_; ++s) {
            a0 = fmaf(r1s[s][0], g_WfT[0 * S2_ + s * S_ + t], a0);
            a1 = fmaf(r1s[s][1], g_WfT[1 * S2_ + s * S_ + t], a1);
            a2 = fmaf(r1s[s][2], g_WfT[2 * S2_ + s * S_ + t], a2);
        }
        float* o = out + (b * S_ + t) * 3;
        o[0] = a0; o[1] = a1; o[2] = a2;
    }
}

// ---------------- launch ----------------
extern "C" void kernel_launch(void* const* d_in, const int* in_sizes, int n_in,
                              void* d_out, int out_size) {
    const float* x     = (const float*)d_in[0];
    const float* c3    = (const float*)d_in[1];
    const float* l3    = (const float*)d_in[2];
    const float* c6    = (const float*)d_in[3];
    const float* l6    = (const float*)d_in[4];
    const float* c12   = (const float*)d_in[5];
    const float* l12   = (const float*)d_in[6];
    const float* c24   = (const float*)d_in[7];
    const float* l24   = (const float*)d_in[8];
    const float* Wb0   = (const float*)d_in[9];
    const float* bb0   = (const float*)d_in[10];
    const float* Wb1   = (const float*)d_in[11];
    const float* bb1   = (const float*)d_in[12];
    const float* Wff1  = (const float*)d_in[13];
    const float* bff1  = (const float*)d_in[14];
    const float* Wff2  = (const float*)d_in[15];
    const float* bff2  = (const float*)d_in[16];
    const float* Wta   = (const float*)d_in[17];
    const float* bta   = (const float*)d_in[18];
    const float* Wtb   = (const float*)d_in[19];
    const float* btb   = (const float*)d_in[20];
    const float* Wfc   = (const float*)d_in[21];
    const float* bfc   = (const float*)d_in[22];
    const float* Wfits = (const float*)d_in[23];
    float* out = (float*)d_out;

    const int SMEM_RNN = 222352;
    cudaFuncSetAttribute(k_rnn, cudaFuncAttributeMaxDynamicSharedMemorySize, SMEM_RNN);

    const int NPRE = (16 * 9 * 32 + 16 * 16 * 32 + 24 * 16 * 32 + 384) + 6 * S2_;
    k_preall<<<(NPRE + 255) / 256, 256>>>(Wb0, Wb1, Wff1, Wff2, Wta, Wtb,
                                          bff1, bff2, bta, btb,
                                          c3, l3, c6, l6, c12, l12, c24, l24, Wfits);
    k_mean<<<(B_ * F_ * 32 + 255) / 256, 256>>>(x);
    k_front<<<B_, 192>>>(x);
    k_rnn<<<128, 512, SMEM_RNN>>>(bb0, bb1);
    k_back<<<B_, 256>>>(Wfc, bfc, out);
}

// round 17
// speedup vs baseline: 1.0711x; 1.0711x over previous
#include <cuda_runtime.h>
#include <cuda_fp16.h>

#define B_ 512
#define S_ 168
#define F_ 12
#define H_ 128
#define O_ 3
#define S2_ (S_ * S_)
#define ROWS 8

typedef unsigned int u32;

// ---------------- device scratch ----------------
__device__ uint4 g_W0f[16 * 9 * 32];    // L0 fragments [tile][ks][lane] (K=144: x|pad|h)
__device__ uint4 g_W1f[16 * 16 * 32];   // L1 fragments [tile][ks][lane]
__device__ uint4 g_Hf[24 * 16 * 32];    // head fragments (per-rank blocks [ff1|ff2|gate])
__device__ float g_bh[384];
__device__ float g_T[3 * S2_];
__device__ float g_WfT[3 * S2_];
__device__ float g_mean[B_ * F_];
__device__ float g_x1[B_ * S_ * F_];
__device__ float g_x2[B_ * S_ * O_];
__device__ float g_x3[B_ * S_ * O_];
__device__ float g_hs[B_ * S_ * H_];

// ---------------- helpers ----------------
__device__ __forceinline__ float tanh_ap(float x) {
    float y;
    asm("tanh.approx.f32 %0, %1;" : "=f"(y) : "f"(x));
    return y;
}
__device__ __forceinline__ float siluf(float x) {
    return x * fmaf(0.5f, tanh_ap(0.5f * x), 0.5f);
}
__device__ __forceinline__ float sigf(float x) {
    return fmaf(0.5f, tanh_ap(0.5f * x), 0.5f);
}
__device__ __forceinline__ u32 hpack(float a, float b) {
    __half2 h = __floats2half2_rn(a, b);
    return *reinterpret_cast<u32*>(&h);
}
__device__ __forceinline__ void mma16816(float* d, uint4 A, u32 b0, u32 b1) {
    asm volatile(
        "mma.sync.aligned.m16n8k16.row.col.f32.f16.f16.f32 "
        "{%0,%1,%2,%3},{%4,%5,%6,%7},{%8,%9},{%0,%1,%2,%3};"
        : "+f"(d[0]), "+f"(d[1]), "+f"(d[2]), "+f"(d[3])
        : "r"(A.x), "r"(A.y), "r"(A.z), "r"(A.w), "r"(b0), "r"(b1));
}
#define CLUSTER_SYNC() do { \
    asm volatile("barrier.cluster.arrive.aligned;" ::: "memory"); \
    asm volatile("barrier.cluster.wait.aligned;" ::: "memory"); } while (0)

__device__ __forceinline__ void st_async32(u32 raddr, u32 v, u32 rmbar) {
    asm volatile(
        "st.async.shared::cluster.mbarrier::complete_tx::bytes.b32 [%0], %1, [%2];"
        :: "r"(raddr), "r"(v), "r"(rmbar) : "memory");
}
__device__ __forceinline__ void mbar_init(u32 a, u32 cnt) {
    asm volatile("mbarrier.init.shared.b64 [%0], %1;" :: "r"(a), "r"(cnt) : "memory");
}
__device__ __forceinline__ void mbar_expect(u32 a, u32 bytes) {
    asm volatile("mbarrier.arrive.expect_tx.shared.b64 _, [%0], %1;"
                 :: "r"(a), "r"(bytes) : "memory");
}
__device__ __forceinline__ void mbar_wait(u32 a, u32 parity) {
    asm volatile(
        "{\n\t.reg .pred P;\n"
        "W%=:\n\t"
        "mbarrier.try_wait.parity.acquire.cluster.shared::cta.b64 P, [%0], %1, 0x989680;\n\t"
        "@P bra D%=;\n\t"
        "bra W%=;\n"
        "D%=:\n\t}"
        :: "r"(a), "r"(parity) : "memory");
}

// weight element accessors
// L0 K layout: [0,12)=x, [12,16)=pad, [16,144)=h
__device__ __forceinline__ float w0_at(const float* W, int o, int k) {
    if (k < 12)  return W[o * 140 + k];
    if (k < 16)  return 0.f;
    return W[o * 140 + (k - 4)];
}
// head reorder: block r (192 rows) = [ff1(64r:64r+64); ff2(...); gate(...)]
__device__ __forceinline__ float wh_at(const float* f1, const float* f2,
                                       const float* ta, const float* tb, int m, int k) {
    int blk = m / 192, o = m % 192, base = blk * 64;
    if (o < 64)  return f1[(base + o) * 256 + k];
    if (o < 128) return f2[(base + o - 64) * 256 + k];
    return ta[(base + o - 128) * 256 + k] + tb[(base + o - 128) * 256 + k];
}

__device__ __forceinline__ float sff_contrib(const float* __restrict__ conv,
                                             const float* __restrict__ lin,
                                             int p, int seg, int pad, int so, int si) {
    int phase = so % p, q = so / p;
    float acc = 0.f;
    for (int kk = 0; kk < seg; ++kk) {
        int d = si - (kk * p + phase);
        float c = 0.f;
        if (d >= -pad && d <= pad) c = conv[d + pad];
        if (d == 0) c += 1.f;
        acc += lin[q * seg + kk] * c;
    }
    return acc;
}

// ---------------- merged prep: fragments + biases + T + WfT ----------------
__global__ void k_preall(const float* __restrict__ Wb0, const float* __restrict__ Wb1,
                         const float* __restrict__ Wff1, const float* __restrict__ Wff2,
                         const float* __restrict__ Wta, const float* __restrict__ Wtb,
                         const float* __restrict__ bff1, const float* __restrict__ bff2,
                         const float* __restrict__ bta, const float* __restrict__ btb,
                         const float* __restrict__ c3, const float* __restrict__ l3,
                         const float* __restrict__ c6, const float* __restrict__ l6,
                         const float* __restrict__ c12, const float* __restrict__ l12,
                         const float* __restrict__ c24, const float* __restrict__ l24,
                         const float* __restrict__ Wfits) {
    int idx = blockIdx.x * blockDim.x + threadIdx.x;
    const int N0 = 16 * 9 * 32, N1 = 16 * 16 * 32, NH = 24 * 16 * 32;
    const int NP = N0 + N1 + NH + 384;
    if (idx < N0 + N1 + NH) {
        int which, tile, ks, l, i = idx;
        if (i < N0)           { which = 0; tile = i / (9 * 32);  ks = (i / 32) % 9; }
        else if (i < N0 + N1) { which = 1; i -= N0; tile = i / (16 * 32); ks = (i / 32) % 16; }
        else                  { which = 2; i -= N0 + N1; tile = i / (16 * 32); ks = (i / 32) % 16; }
        l = i % 32;
        int g = l / 4, ti = l % 4;
        int r0 = tile * 16 + g, k0 = ks * 16 + ti * 2;
        float e[4][2];
        for (int half = 0; half < 2; half++) {
            for (int rr = 0; rr < 2; rr++) {
                for (int cc = 0; cc < 2; cc++) {
                    int o = r0 + rr * 8, k = k0 + half * 8 + cc;
                    float wv;
                    if (which == 0)      wv = w0_at(Wb0, o, k);
                    else if (which == 1) wv = Wb1[o * 256 + k];
                    else                 wv = wh_at(Wff1, Wff2, Wta, Wtb, o, k);
                    e[half * 2 + rr][cc] = wv;
                }
            }
        }
        uint4 out;
        out.x = hpack(e[0][0], e[0][1]);
        out.y = hpack(e[1][0], e[1][1]);
        out.z = hpack(e[2][0], e[2][1]);
        out.w = hpack(e[3][0], e[3][1]);
        if (which == 0)      g_W0f[idx] = out;
        else if (which == 1) g_W1f[idx - N0] = out;
        else                 g_Hf[idx - N0 - N1] = out;
    } else if (idx < NP) {
        int m = idx - N0 - N1 - NH;
        int blk = m / 192, o = m % 192, base = blk * 64;
        float b;
        if (o < 64)       b = bff1[base + o];
        else if (o < 128) b = bff2[base + o - 64];
        else              b = bta[base + o - 128] + btb[base + o - 128];
        g_bh[m] = b;
    } else if (idx < NP + 3 * S2_) {
        int j = idx - NP;
        int L = j / S2_, r = j % S2_;
        int so = r / S_, si = r % S_;
        float a = sff_contrib(c3 + L * 3, l3 + L * 56 * 56, 3, 56, 1, so, si)
                + sff_contrib(c6 + L * 7, l6 + L * 28 * 28, 6, 28, 3, so, si)
                + sff_contrib(c12 + L * 13, l12 + L * 14 * 14, 12, 14, 6, so, si)
                + sff_contrib(c24 + L * 25, l24 + L * 7 * 7, 24, 7, 12, so, si);
        g_T[L * S2_ + si * S_ + so] = 0.25f * a;
    } else if (idx < NP + 6 * S2_) {
        int j = idx - NP - 3 * S2_;
        int c = j / S2_, r = j % S2_;
        int s = r / S_, p = r % S_;
        g_WfT[c * S2_ + s * S_ + p] = Wfits[c * S2_ + p * S_ + s];
    }
}

__global__ void k_mean(const float* __restrict__ x) {
    int w = (blockIdx.x * blockDim.x + threadIdx.x) >> 5;
    int lane = threadIdx.x & 31;
    if (w >= B_ * F_) return;
    const float* p = x + w * S_;
    float s = 0.f;
    for (int i = lane; i < S_; i += 32) s += p[i];
#pragma unroll
    for (int o = 16; o; o >>= 1) s += __shfl_xor_sync(0xffffffffu, s, o);
    if (!lane) g_mean[w] = s * (1.f / (float)S_);
}

// ---------------- fused front ----------------
__global__ void k_front(const float* __restrict__ x) {
    __shared__ float xs[S_][F_];
    __shared__ float x1s[S_][4];
    int b = blockIdx.x, t = threadIdx.x;
    for (int i = t; i < S_ * F_; i += blockDim.x) {
        int si = i / F_, f = i % F_;
        xs[si][f] = x[b * F_ * S_ + f * S_ + si] - g_mean[b * F_ + f];
    }
    __syncthreads();
    if (t < S_) {
        float acc[F_];
#pragma unroll
        for (int f = 0; f < F_; f++) acc[f] = 0.f;
        for (int si = 0; si < S_; ++si) {
            float tw = g_T[si * S_ + t];
#pragma unroll
            for (int f = 0; f < F_; f++) acc[f] = fmaf(tw, xs[si][f], acc[f]);
        }
        float* o = g_x1 + (b * S_ + t) * F_;
#pragma unroll
        for (int f = 0; f < F_; f++) o[f] = acc[f];
        x1s[t][0] = acc[0]; x1s[t][1] = acc[1]; x1s[t][2] = acc[2];
    }
    __syncthreads();
    if (t < S_) {
        float a2[3] = {0.f, 0.f, 0.f}, a3[3] = {0.f, 0.f, 0.f};
        for (int si = 0; si < S_; ++si) {
            float t1 = g_T[S2_ + si * S_ + t];
            float t2 = g_T[2 * S2_ + si * S_ + t];
#pragma unroll
            for (int c = 0; c < 3; c++) {
                a2[c] = fmaf(t1, x1s[si][c], a2[c]);
                a3[c] = fmaf(t2, x1s[si][c], a3[c]);
            }
        }
#pragma unroll
        for (int c = 0; c < 3; c++) {
            g_x2[(b * S_ + t) * 3 + c] = a2[c];
            g_x3[(b * S_ + t) * 3 + c] = a3[c];
        }
    }
}

// ---------------- CfC recurrence: cluster-2, st.async, triplet head ----------
// 256 threads. tx per step: mb_h = 128 lanes x 2 x 4 B = 1024; mb_p = 4096.
// Head: warp w in 0..3 computes tiles {w, 4+w, 8+w} = (ff1|ff2|gate) for the
// SAME 16 outputs -> CfC combine is register-local; h is sent via st.async
// right after the head MMAs (no hdro smem roundtrip, no extra sync).
// Warps 4-7 do the x(s+1) prefetch/write during the head phase.
// SMEM (bytes):
//   [0,36864)       sW0 | [36864,102400) sW1 | [102400,200704) sHf
//   [200704,203392) in0 [8][168]h | [203392,207616) za [8][264]h
//   [207616,211712) pB col-major [256][8]h | [211712,215936) zb [8][264]h
//   [215936,215952) mb_h, mb_p
__global__ void __launch_bounds__(256, 1) __cluster_dims__(2, 1, 1)
k_rnn(const float* __restrict__ bb0, const float* __restrict__ bb1) {
    extern __shared__ __align__(16) char s[];
    uint4*  sW0  = (uint4*)(s);
    uint4*  sW1  = (uint4*)(s + 36864);
    uint4*  sHf  = (uint4*)(s + 102400);
    __half* in0  = (__half*)(s + 200704);
    __half* za   = (__half*)(s + 203392);
    char*   pB   = (char*)(s + 207616);
    __half* zb   = (__half*)(s + 211712);

    const int t = threadIdx.x, w = t >> 5, l = t & 31, gg = l >> 2, ti = l & 3;
    u32 rank;
    asm("mov.u32 %0, %%cluster_ctarank;" : "=r"(rank));
    const u32 peer = rank ^ 1u;
    const int bb = (blockIdx.x >> 1) * ROWS;

    u32 base;
    asm("{ .reg .u64 a; cvta.to.shared.u64 a, %1; cvt.u32.u64 %0, a; }" : "=r"(base) : "l"(s));
    const u32 mb_h = base + 215936, mb_p = base + 215944;
    u32 in0_r, pB_r, mb_h_r, mb_p_r;
    asm("mapa.shared::cluster.u32 %0, %1, %2;" : "=r"(in0_r) : "r"(base + 200704), "r"(peer));
    asm("mapa.shared::cluster.u32 %0, %1, %2;" : "=r"(pB_r) : "r"(base + 207616), "r"(peer));
    asm("mapa.shared::cluster.u32 %0, %1, %2;" : "=r"(mb_h_r) : "r"(mb_h), "r"(peer));
    asm("mapa.shared::cluster.u32 %0, %1, %2;" : "=r"(mb_p_r) : "r"(mb_p), "r"(peer));

    // stage weights
    {
        const uint4* p0 = g_W0f + rank * 2304;
        for (int i = t; i < 2304; i += 256) sW0[i] = p0[i];
        for (int i = t; i < 4096; i += 256) {
            int tile = i >> 8, ksl = (i >> 5) & 7, lane = i & 31;
            sW1[i] = g_W1f[(tile * 16 + 8 * (int)rank + ksl) * 32 + lane];
        }
        const uint4* ph = g_Hf + rank * 6144;
        for (int i = t; i < 6144; i += 256) sHf[i] = ph[i];
    }
    for (int i = t; i < ROWS * 168; i += 256) in0[i] = __float2half(0.f);
    if (t == 0) {
        mbar_init(mb_h, 1);
        mbar_init(mb_p, 1);
        mbar_expect(mb_h, 0);      // h(-1)=0 -> phase 0 completes now
        mbar_expect(mb_p, 4096);   // step-0 partials
    }
    __syncthreads();
    CLUSTER_SYNC();            // init + expects + zeroed h visible cluster-wide
    if (t < 96) {              // x(0)
        int r = t / 12, f = t - r * 12;
        in0[r * 168 + f] = __float2half(g_x1[(bb + r) * S_ * F_ + f]);
    }

    const int ra2 = 2 * ti, rb2 = 2 * ti + 1;
    const int hb = 192 * (int)rank;
    const int gob = (8 * (int)rank + w) * 16;
    const int ko1 = 1 + 4 * (int)rank, kp1 = 1 + 4 * (int)peer;
    const int t0 = 2 * w, t1 = 2 * w + 1;
    const int o0 = t0 * 16 + gg, o1 = t1 * 16 + gg;
    const bool hw_ = (w < 4);

    // bias preloads
    const float rb0a = bb0[gob + gg], rb0b = bb0[gob + gg + 8];
    const float rb1c0 = bb1[o0],  rb1c1 = bb1[o0 + 8];
    const float rb1c2 = bb1[o1],  rb1c3 = bb1[o1 + 8];
    const float b1a = hw_ ? g_bh[hb + w * 16 + gg] : 0.f;
    const float b1b = hw_ ? g_bh[hb + w * 16 + gg + 8] : 0.f;
    const float b2a = hw_ ? g_bh[hb + (4 + w) * 16 + gg] : 0.f;
    const float b2b = hw_ ? g_bh[hb + (4 + w) * 16 + gg + 8] : 0.f;
    const float bga = hw_ ? g_bh[hb + (8 + w) * 16 + gg] : 0.f;
    const float bgb = hw_ ? g_bh[hb + (8 + w) * 16 + gg + 8] : 0.f;

    for (int step = 0; step < S_; ++step) {
        const u32 par = step & 1u;
        __syncthreads();   // local in0 (x(s), own h(s-1)) visible

        // ======== L0: own 8 tiles, K=144 (x + own-h, [wait], peer-h) ========
        float dA[4], dB[4];
        {
            dA[0] = dA[1] = rb0a;
            dA[2] = dA[3] = rb0b;
            dB[0] = dB[1] = dB[2] = dB[3] = 0.f;
            {
                u32 b0 = *(const u32*)&in0[gg * 168 + ti * 2];
                u32 b1 = *(const u32*)&in0[gg * 168 + ti * 2 + 8];
                mma16816(dA, sW0[(w * 9 + 0) * 32 + l], b0, b1);
            }
#pragma unroll
            for (int j = 0; j < 4; j++) {
                int ks = ko1 + j;
                u32 b0 = *(const u32*)&in0[gg * 168 + ks * 16 + ti * 2];
                u32 b1 = *(const u32*)&in0[gg * 168 + ks * 16 + ti * 2 + 8];
                mma16816((j & 1) ? dB : dA, sW0[(w * 9 + ks) * 32 + l], b0, b1);
            }
        }
        mbar_wait(mb_h, par);   // peer h(s-1) landed
        // next h expect: ordered before peer h(s)-complete (that needs our
        // partials(s), stored after the za sync below)
        if (t == 0 && step + 1 < S_) mbar_expect(mb_h, 1024);
        {
#pragma unroll
            for (int j = 0; j < 4; j++) {
                int ks = kp1 + j;
                u32 b0 = *(const u32*)&in0[gg * 168 + ks * 16 + ti * 2];
                u32 b1 = *(const u32*)&in0[gg * 168 + ks * 16 + ti * 2 + 8];
                mma16816((j & 1) ? dA : dB, sW0[(w * 9 + ks) * 32 + l], b0, b1);
            }
            int i0 = ra2 * 264 + gob + gg, i1 = rb2 * 264 + gob + gg;
            za[i0]     = __float2half(siluf(dA[0] + dB[0]));
            za[i1]     = __float2half(siluf(dA[1] + dB[1]));
            za[i0 + 8] = __float2half(siluf(dA[2] + dB[2]));
            za[i1 + 8] = __float2half(siluf(dA[3] + dB[3]));
        }
        __syncthreads();   // za complete; orders t0's h-expect before partial sends

        // ======== L1 K-split: ALL 256 outs over own za half (4 chains) ======
        float d0[4], d1[4];
        {
            float d0a[4] = {0.f, 0.f, 0.f, 0.f}, d0b[4] = {0.f, 0.f, 0.f, 0.f};
            float d1a[4] = {0.f, 0.f, 0.f, 0.f}, d1b[4] = {0.f, 0.f, 0.f, 0.f};
#pragma unroll
            for (int j = 0; j < 8; j++) {
                int ksg = 8 * (int)rank + j;
                u32 b0 = *(const u32*)&za[gg * 264 + ksg * 16 + ti * 2];
                u32 b1 = *(const u32*)&za[gg * 264 + ksg * 16 + ti * 2 + 8];
                mma16816((j & 1) ? d0b : d0a, sW1[(t0 * 8 + j) * 32 + l], b0, b1);
                mma16816((j & 1) ? d1b : d1a, sW1[(t1 * 8 + j) * 32 + l], b0, b1);
            }
#pragma unroll
            for (int j = 0; j < 4; j++) {
                d0[j] = d0a[j] + d0b[j];
                d1[j] = d1a[j] + d1b[j];
            }
            st_async32(pB_r + o0 * 16 + ti * 4,       hpack(d0[0], d0[1]), mb_p_r);
            st_async32(pB_r + (o0 + 8) * 16 + ti * 4, hpack(d0[2], d0[3]), mb_p_r);
            st_async32(pB_r + o1 * 16 + ti * 4,       hpack(d1[0], d1[1]), mb_p_r);
            st_async32(pB_r + (o1 + 8) * 16 + ti * 4, hpack(d1[2], d1[3]), mb_p_r);
        }
        // warps 4-6 prefetch x(s+1) into registers while waiting
        float xreg = 0.f;
        const int tx = t - 128;
        if (tx >= 0 && tx < 96 && step + 1 < S_) {
            int r = tx / 12, f = tx - r * 12;
            xreg = __ldg(&g_x1[((bb + r) * S_ + step + 1) * F_ + f]);
        }
        mbar_wait(mb_p, par);   // peer partial landed
        // next p expect: ordered before peer partial(s+1)-complete (that needs
        // our h(s); t0's h sends follow this in t0's program order, and peer
        // needs ALL 1024 B of our h, so the chain holds)
        if (t == 0 && step + 1 < S_) mbar_expect(mb_p, 4096);

        // ======== zb fuse: regs + pB + bias ========
        {
            float2 q;
            q = __half22float2(*(const __half2*)(pB + o0 * 16 + ti * 4));
            zb[ra2 * 264 + o0] = __float2half(siluf(d0[0] + q.x + rb1c0));
            zb[rb2 * 264 + o0] = __float2half(siluf(d0[1] + q.y + rb1c0));
            q = __half22float2(*(const __half2*)(pB + (o0 + 8) * 16 + ti * 4));
            zb[ra2 * 264 + o0 + 8] = __float2half(siluf(d0[2] + q.x + rb1c1));
            zb[rb2 * 264 + o0 + 8] = __float2half(siluf(d0[3] + q.y + rb1c1));
            q = __half22float2(*(const __half2*)(pB + o1 * 16 + ti * 4));
            zb[ra2 * 264 + o1] = __float2half(siluf(d1[0] + q.x + rb1c2));
            zb[rb2 * 264 + o1] = __float2half(siluf(d1[1] + q.y + rb1c2));
            q = __half22float2(*(const __half2*)(pB + (o1 + 8) * 16 + ti * 4));
            zb[ra2 * 264 + o1 + 8] = __float2half(siluf(d1[2] + q.x + rb1c3));
            zb[rb2 * 264 + o1 + 8] = __float2half(siluf(d1[3] + q.y + rb1c3));
        }
        __syncthreads();   // zb complete

        // ======== head (warps 0-3): triplet tiles {w,4+w,8+w}; reg combine ===
        if (hw_) {
            float e1a[4], e1b[4], e2a[4], e2b[4], ega[4], egb[4];
            e1a[0] = e1a[1] = b1a; e1a[2] = e1a[3] = b1b;
            e2a[0] = e2a[1] = b2a; e2a[2] = e2a[3] = b2b;
            ega[0] = ega[1] = bga; ega[2] = ega[3] = bgb;
#pragma unroll
            for (int j = 0; j < 4; j++) { e1b[j] = 0.f; e2b[j] = 0.f; egb[j] = 0.f; }
#pragma unroll
            for (int ks = 0; ks < 16; ks++) {
                u32 b0 = *(const u32*)&zb[gg * 264 + ks * 16 + ti * 2];
                u32 b1 = *(const u32*)&zb[gg * 264 + ks * 16 + ti * 2 + 8];
                mma16816((ks & 1) ? e1b : e1a, sHf[(w * 16 + ks) * 32 + l], b0, b1);
                mma16816((ks & 1) ? e2b : e2a, sHf[((4 + w) * 16 + ks) * 32 + l], b0, b1);
                mma16816((ks & 1) ? egb : ega, sHf[((8 + w) * 16 + ks) * 32 + l], b0, b1);
            }
            // register combine: lane holds h for (rows 2ti/2ti+1) x (cols ob+gg, ob+gg+8)
            float h[4];
#pragma unroll
            for (int j = 0; j < 4; j++) {
                float f1 = tanh_ap(e1a[j] + e1b[j]);
                float f2 = tanh_ap(e2a[j] + e2b[j]);
                float sg = sigf(ega[j] + egb[j]);
                h[j] = f1 + sg * (f2 - f1);
            }
            // butterfly pack (lanes gg <-> gg^1): even lane keeps row 2ti,
            // odd lane keeps row 2ti+1, each with two adjacent-col pairs
            const bool ev = !(gg & 1);
            float s1v = ev ? h[1] : h[0];
            float s3v = ev ? h[3] : h[2];
            float r1v = __shfl_xor_sync(0xffffffffu, s1v, 4);
            float r3v = __shfl_xor_sync(0xffffffffu, s3v, 4);
            float pa0 = ev ? h[0] : r1v, pa1 = ev ? r1v : h[1];
            float pb0 = ev ? h[2] : r3v, pb1 = ev ? r3v : h[3];
            int row = ev ? ra2 : rb2;
            int cb = w * 16 + (gg & ~1);
            int jg = 64 * (int)rank + cb;
            int idx = row * 168 + 16 + jg;
            u32 hh0 = hpack(pa0, pa1), hh1 = hpack(pb0, pb1);
            if (step + 1 < S_) {
                st_async32(in0_r + idx * 2, hh0, mb_h_r);        // send first
                st_async32(in0_r + (idx + 8) * 2, hh1, mb_h_r);
            }
            *(u32*)&in0[idx] = hh0;
            *(u32*)&in0[idx + 8] = hh1;
            float* gh = &g_hs[((size_t)(bb + row) * S_ + step) * H_ + jg];
            *(float2*)gh = make_float2(pa0, pa1);
            *(float2*)(gh + 8) = make_float2(pb0, pb1);
        } else {
            // warps 4-6: write x(s+1)
            if (tx < 96 && step + 1 < S_) {
                int r = tx / 12, f = tx - r * 12;
                in0[r * 168 + f] = __float2half(xreg);
            }
        }
    }
    CLUSTER_SYNC();   // drain
}

// ---------------- fused back ----------------
__global__ void k_back(const float* __restrict__ Wfc, const float* __restrict__ bfc,
                       float* __restrict__ out) {
    __shared__ float r1s[S_][4];
    int b = blockIdx.x, t = threadIdx.x;
    int w = t >> 5, lane = t & 31;
    for (int s = w; s < S_; s += 8) {
        const float* h = g_hs + (size_t)(b * S_ + s) * H_;
        float a0 = 0.f, a1 = 0.f, a2 = 0.f;
        for (int i = lane; i < H_; i += 32) {
            float hv = h[i];
            a0 = fmaf(hv, Wfc[i], a0);
            a1 = fmaf(hv, Wfc[H_ + i], a1);
            a2 = fmaf(hv, Wfc[2 * H_ + i], a2);
        }
#pragma unroll
        for (int o = 16; o; o >>= 1) {
            a0 += __shfl_xor_sync(0xffffffffu, a0, o);
            a1 += __shfl_xor_sync(0xffffffffu, a1, o);
            a2 += __shfl_xor_sync(0xffffffffu, a2, o);
        }
        if (!lane) {
            r1s[s][0] = a0 + bfc[0] + g_x3[(b * S_ + s) * 3 + 0];
            r1s[s][1] = a1 + bfc[1] + g_x3[(b * S_ + s) * 3 + 1];
            r1s[s][2] = a2 + bfc[2] + g_x3[(b * S_ + s) * 3 + 2];
        }
    }
    __syncthreads();
    if (t < S_) {
        float a0 = g_mean[b * F_ + 0] + g_x2[(b * S_ + t) * 3 + 0];
        float a1 = g_mean[b * F_ + 1] + g_x2[(b * S_ + t) * 3 + 1];
        float a2 = g_mean[b * F_ + 2] + g_x2[(b * S_ + t) * 3 + 2];
        for (int s = 0; s < S_; ++s) {
            a0 = fmaf(r1s[s][0], g_WfT[0 * S2_ + s * S_ + t], a0);
            a1 = fmaf(r1s[s][1], g_WfT[1 * S2_ + s * S_ + t], a1);
            a2 = fmaf(r1s[s][2], g_WfT[2 * S2_ + s * S_ + t], a2);
        }
        float* o = out + (b * S_ + t) * 3;
        o[0] = a0; o[1] = a1; o[2] = a2;
    }
}

// ---------------- launch ----------------
extern "C" void kernel_launch(void* const* d_in, const int* in_sizes, int n_in,
                              void* d_out, int out_size) {
    const float* x     = (const float*)d_in[0];
    const float* c3    = (const float*)d_in[1];
    const float* l3    = (const float*)d_in[2];
    const float* c6    = (const float*)d_in[3];
    const float* l6    = (const float*)d_in[4];
    const float* c12   = (const float*)d_in[5];
    const float* l12   = (const float*)d_in[6];
    const float* c24   = (const float*)d_in[7];
    const float* l24   = (const float*)d_in[8];
    const float* Wb0   = (const float*)d_in[9];
    const float* bb0   = (const float*)d_in[10];
    const float* Wb1   = (const float*)d_in[11];
    const float* bb1   = (const float*)d_in[12];
    const float* Wff1  = (const float*)d_in[13];
    const float* bff1  = (const float*)d_in[14];
    const float* Wff2  = (const float*)d_in[15];
    const float* bff2  = (const float*)d_in[16];
    const float* Wta   = (const float*)d_in[17];
    const float* bta   = (const float*)d_in[18];
    const float* Wtb   = (const float*)d_in[19];
    const float* btb   = (const float*)d_in[20];
    const float* Wfc   = (const float*)d_in[21];
    const float* bfc   = (const float*)d_in[22];
    const float* Wfits = (const float*)d_in[23];
    float* out = (float*)d_out;

    const int SMEM_RNN = 215952;
    cudaFuncSetAttribute(k_rnn, cudaFuncAttributeMaxDynamicSharedMemorySize, SMEM_RNN);

    const int NPRE = (16 * 9 * 32 + 16 * 16 * 32 + 24 * 16 * 32 + 384) + 6 * S2_;
    k_preall<<<(NPRE + 255) / 256, 256>>>(Wb0, Wb1, Wff1, Wff2, Wta, Wtb,
                                          bff1, bff2, bta, btb,
                                          c3, l3, c6, l6, c12, l12, c24, l24, Wfits);
    k_mean<<<(B_ * F_ * 32 + 255) / 256, 256>>>(x);
    k_front<<<B_, 192>>>(x);
    k_rnn<<<128, 256, SMEM_RNN>>>(bb0, bb1);
    k_back<<<B_, 256>>>(Wfc, bfc, out);
}